// round 7
// baseline (speedup 1.0000x reference)
#include <cuda_runtime.h>
#include <cstdint>
#include <cstddef>

#define IN_CH  64
#define OUT_CH 128
#define TILE_M 128

// ---------------- BN scratch + grid barrier (no allocs allowed) ----------------
__device__ float g_sum[OUT_CH];
__device__ float g_sqsum[OUT_CH];
__device__ unsigned int g_bar;

__global__ void zero_stats_kernel() {
    int c = threadIdx.x;
    g_sum[c]   = 0.f;
    g_sqsum[c] = 0.f;
    if (c == 0) g_bar = 0u;
}

__device__ __forceinline__ uint32_t cvt_tf32(float f) {
    uint32_t r;
    asm("cvt.rna.tf32.f32 %0, %1;" : "=r"(r) : "f"(f));
    return r;
}

// ---------------- mask dtype detection (bool widened to ?) ----------------
__device__ __forceinline__ int detect_mask_mode(const void* mask) {
    int w = ((const int*)mask)[0];
    if (w == 1) return 1;                       // int32
    if (__int_as_float(w) == 1.0f) return 2;    // float32
    return 0;                                   // bytes
}
__device__ __forceinline__ bool mask_at(const void* mask, int mode, long i) {
    if (mode == 1) return ((const int*)mask)[i] != 0;
    if (mode == 2) return ((const float*)mask)[i] != 0.0f;
    return ((const unsigned char*)mask)[i] != 0;
}

// smem layout (bytes)
#define A_STRIDE 68               // 64 + 4 pad
#define B_STRIDE 136              // 128 + 8 pad
#define SM_VI 0                   // int[128]
#define SM_VO 512                 // int[128]
#define SM_A  1024                // u32[128*68]
#define SM_B  (SM_A + TILE_M * A_STRIDE * 4)
#define SM_TOTAL (SM_B + IN_CH * B_STRIDE * 4)    // 70656 B

// ---------------------------------------------------------------------------
// Per block: one k, 128 rules. Gather -> tf32 mma.sync (M=128,N=128,K=64)
// -> shfl-pack -> red.global.add.v4 scatter.
// grid = (ceil(R/128), 9), block = 256 (8 warps)
// warp w: M rows [ (w>>1)*32, +32 ), N cols [ (w&1)*64, +64 )
// ---------------------------------------------------------------------------
__global__ __launch_bounds__(256) void sp_mma_kernel(
    const float* __restrict__ feats,
    const float* __restrict__ W,
    const int*   __restrict__ in_idx,
    const int*   __restrict__ out_idx,
    const void*  __restrict__ mask,
    float* __restrict__ out,
    int R)
{
    extern __shared__ char smem[];
    int*      svi = (int*)(smem + SM_VI);
    int*      svo = (int*)(smem + SM_VO);
    uint32_t* sA  = (uint32_t*)(smem + SM_A);
    uint32_t* sB  = (uint32_t*)(smem + SM_B);

    const int tid  = threadIdx.x;
    const int warp = tid >> 5;
    const int lane = tid & 31;
    const int k    = blockIdx.y;

    // ---- rule metadata (threads 0..127 handle one rule each) ----
    const int mmode = detect_mask_mode(mask);
    bool valid = false;
    if (tid < TILE_M) {
        const long r = (long)blockIdx.x * TILE_M + tid;
        int vi = 0, vo = -1;
        if (r < R) {
            const long gi = (long)k * R + r;
            valid = mask_at(mask, mmode, gi);
            if (valid) { vi = in_idx[gi]; vo = out_idx[gi]; }
        }
        svi[tid] = vi;
        svo[tid] = vo;
    }
    // valid rules are front-packed per k-row -> padded tail blocks exit whole
    if (__syncthreads_count(tid < TILE_M ? (int)valid : 0) == 0) return;

    // ---- stage B = W[k] ([64 K][128 N], tf32, padded) ----
    {
        const float* Wk = W + (size_t)k * IN_CH * OUT_CH;
        #pragma unroll
        for (int i = 0; i < (IN_CH * OUT_CH) / 256; i++) {
            int idx = tid + i * 256;
            int c = idx >> 7, n = idx & 127;
            sB[c * B_STRIDE + n] = cvt_tf32(Wk[idx]);   // coalesced
        }
    }

    // ---- gather A rows (2 threads per row, 32 floats each) ----
    {
        const int row = tid >> 1, half = tid & 1;
        const int vi = svi[row];
        const bool rv = (svo[row] >= 0);
        const float4* src = (const float4*)(feats + (size_t)vi * IN_CH) + half * 8;
        uint4* dst = (uint4*)(sA + row * A_STRIDE + half * 32);
        #pragma unroll
        for (int j = 0; j < 8; j++) {
            uint4 o = make_uint4(0u, 0u, 0u, 0u);
            if (rv) {
                float4 v = src[j];
                o.x = cvt_tf32(v.x); o.y = cvt_tf32(v.y);
                o.z = cvt_tf32(v.z); o.w = cvt_tf32(v.w);
            }
            dst[j] = o;
        }
    }
    __syncthreads();

    // ---- MMA: each warp 2 M-tiles x 8 N-tiles, 8 K-steps of k=8 ----
    const int g = lane >> 2, t = lane & 3;
    const int mbase = (warp >> 1) * 32;
    const int nbase = (warp & 1) * 64;

    float acc[2][8][4];
    #pragma unroll
    for (int mt = 0; mt < 2; mt++)
        #pragma unroll
        for (int nt = 0; nt < 8; nt++)
            #pragma unroll
            for (int j = 0; j < 4; j++) acc[mt][nt][j] = 0.f;

    #pragma unroll
    for (int ks = 0; ks < 8; ks++) {
        const int k0 = ks * 8;
        uint32_t a[2][4];
        #pragma unroll
        for (int mt = 0; mt < 2; mt++) {
            const int rg = mbase + mt * 16 + g;
            a[mt][0] = sA[(rg)     * A_STRIDE + k0 + t];
            a[mt][1] = sA[(rg + 8) * A_STRIDE + k0 + t];
            a[mt][2] = sA[(rg)     * A_STRIDE + k0 + t + 4];
            a[mt][3] = sA[(rg + 8) * A_STRIDE + k0 + t + 4];
        }
        uint32_t b[8][2];
        #pragma unroll
        for (int nt = 0; nt < 8; nt++) {
            const int n = nbase + nt * 8 + g;
            b[nt][0] = sB[(k0 + t)     * B_STRIDE + n];
            b[nt][1] = sB[(k0 + t + 4) * B_STRIDE + n];
        }
        #pragma unroll
        for (int mt = 0; mt < 2; mt++)
            #pragma unroll
            for (int nt = 0; nt < 8; nt++)
                asm("mma.sync.aligned.m16n8k8.row.col.f32.tf32.tf32.f32 "
                    "{%0,%1,%2,%3}, {%4,%5,%6,%7}, {%8,%9}, {%0,%1,%2,%3};"
                    : "+f"(acc[mt][nt][0]), "+f"(acc[mt][nt][1]),
                      "+f"(acc[mt][nt][2]), "+f"(acc[mt][nt][3])
                    : "r"(a[mt][0]), "r"(a[mt][1]), "r"(a[mt][2]), "r"(a[mt][3]),
                      "r"(b[nt][0]), "r"(b[nt][1]));
    }

    // ---- epilogue: shfl-pack lane pairs -> red.global.add.v4 ----
    // lane t=2q holds cols (4q,4q+1) of rows g / g+8; partner t=2q+1 holds
    // (4q+2,4q+3). After bfly(1): even lane emits v4 for row r0, odd lane
    // emits v4 for row r0+8, both at cols nbase+8nt+4q.
    const int q4 = (t >> 1) * 4;
    const bool odd = (t & 1);
    #pragma unroll
    for (int mt = 0; mt < 2; mt++) {
        const int r0 = mbase + mt * 16 + g;
        const int vo = svo[odd ? (r0 + 8) : r0];
        #pragma unroll
        for (int nt = 0; nt < 8; nt++) {
            float p0 = __shfl_xor_sync(0xffffffffu, acc[mt][nt][0], 1);
            float p1 = __shfl_xor_sync(0xffffffffu, acc[mt][nt][1], 1);
            float p2 = __shfl_xor_sync(0xffffffffu, acc[mt][nt][2], 1);
            float p3 = __shfl_xor_sync(0xffffffffu, acc[mt][nt][3], 1);
            float v0, v1, v2, v3;
            if (!odd) { v0 = acc[mt][nt][0]; v1 = acc[mt][nt][1]; v2 = p0; v3 = p1; }
            else      { v0 = p2; v1 = p3; v2 = acc[mt][nt][2]; v3 = acc[mt][nt][3]; }
            if (vo >= 0) {
                float* op = out + (size_t)vo * OUT_CH + nbase + nt * 8 + q4;
                asm volatile("red.global.add.v4.f32 [%0], {%1,%2,%3,%4};" ::
                    "l"(op), "f"(v0), "f"(v1), "f"(v2), "f"(v3) : "memory");
            }
        }
    }
}

// ---------------------------------------------------------------------------
// Fused BN: phase1 stats -> grid barrier -> finalize -> phase2 apply+ReLU.
// grid = 592 blocks x 256 thr, guaranteed co-resident (launch_bounds(256,4)).
// g_bar is zeroed by zero_stats_kernel every launch (graph-replay safe).
// ---------------------------------------------------------------------------
__global__ void __launch_bounds__(256, 4) bn_fused_kernel(
    float* __restrict__ out,
    const float* __restrict__ gamma,
    const float* __restrict__ beta,
    int n_out)
{
    const int tid = threadIdx.x;
    const int c4  = (tid & 31) * 4;          // this thread's 4 channels
    const int rg  = tid >> 5;                // row group 0..7
    const long rstride = (long)gridDim.x * 8;

    // phase 1: partial sums over fixed channels
    float4 s = make_float4(0.f, 0.f, 0.f, 0.f);
    float4 q = make_float4(0.f, 0.f, 0.f, 0.f);
    for (long row = (long)blockIdx.x * 8 + rg; row < n_out; row += rstride) {
        float4 v = *(const float4*)(out + row * OUT_CH + c4);
        s.x += v.x; s.y += v.y; s.z += v.z; s.w += v.w;
        q.x = fmaf(v.x, v.x, q.x); q.y = fmaf(v.y, v.y, q.y);
        q.z = fmaf(v.z, v.z, q.z); q.w = fmaf(v.w, v.w, q.w);
    }
    atomicAdd(&g_sum[c4 + 0], s.x); atomicAdd(&g_sum[c4 + 1], s.y);
    atomicAdd(&g_sum[c4 + 2], s.z); atomicAdd(&g_sum[c4 + 3], s.w);
    atomicAdd(&g_sqsum[c4 + 0], q.x); atomicAdd(&g_sqsum[c4 + 1], q.y);
    atomicAdd(&g_sqsum[c4 + 2], q.z); atomicAdd(&g_sqsum[c4 + 3], q.w);

    // grid barrier
    __threadfence();
    __syncthreads();
    if (tid == 0) {
        atomicAdd(&g_bar, 1u);
        while (*(volatile unsigned int*)&g_bar < gridDim.x) __nanosleep(64);
        __threadfence();
    }
    __syncthreads();

    // finalize (redundant per block, 128 ch)
    __shared__ float s_sc[OUT_CH], s_bi[OUT_CH];
    if (tid < OUT_CH) {
        const float inv_n = 1.0f / (float)n_out;
        float mean = __ldcg(&g_sum[tid]) * inv_n;
        float var  = fmaf(-mean, mean, __ldcg(&g_sqsum[tid]) * inv_n);
        float sc   = gamma[tid] * rsqrtf(var + 1e-5f);
        s_sc[tid] = sc;
        s_bi[tid] = fmaf(-mean, sc, beta[tid]);
    }
    __syncthreads();

    // phase 2: apply + ReLU
    const float4 sc = *(const float4*)&s_sc[c4];
    const float4 bi = *(const float4*)&s_bi[c4];
    for (long row = (long)blockIdx.x * 8 + rg; row < n_out; row += rstride) {
        float4* p = (float4*)(out + row * OUT_CH + c4);
        float4 v = *p;
        v.x = fmaxf(fmaf(v.x, sc.x, bi.x), 0.f);
        v.y = fmaxf(fmaf(v.y, sc.y, bi.y), 0.f);
        v.z = fmaxf(fmaf(v.z, sc.z, bi.z), 0.f);
        v.w = fmaxf(fmaf(v.w, sc.w, bi.w), 0.f);
        *p = v;
    }
}

extern "C" void kernel_launch(void* const* d_in, const int* in_sizes, int n_in,
                              void* d_out, int out_size) {
    const float* feats = (const float*)d_in[0];
    const float* W     = (const float*)d_in[1];
    const float* gamma = (const float*)d_in[2];
    const float* beta  = (const float*)d_in[3];
    const int*   inI   = (const int*)d_in[4];
    const int*   outI  = (const int*)d_in[5];
    const void*  mask  = (const void*)d_in[6];
    float* out = (float*)d_out;

    const int R     = in_sizes[4] / 9;
    const int n_out = out_size / OUT_CH;

    cudaMemsetAsync(d_out, 0, (size_t)out_size * sizeof(float));
    zero_stats_kernel<<<1, OUT_CH>>>();

    cudaFuncSetAttribute(sp_mma_kernel,
                         cudaFuncAttributeMaxDynamicSharedMemorySize, SM_TOTAL);
    dim3 grid((R + TILE_M - 1) / TILE_M, 9);
    sp_mma_kernel<<<grid, 256, SM_TOTAL>>>(feats, W, inI, outI, mask, out, R);

    bn_fused_kernel<<<592, 256>>>(out, gamma, beta, n_out);
}

// round 10
// speedup vs baseline: 1.4807x; 1.4807x over previous
#include <cuda_runtime.h>
#include <cstdint>
#include <cstddef>

#define IN_CH  64
#define OUT_CH 128
#define TILE_M 128

// ---------------- BN scratch (no allocs allowed) ----------------
__device__ float g_sum[OUT_CH];
__device__ float g_sqsum[OUT_CH];
__device__ float g_scale[OUT_CH];
__device__ float g_bias[OUT_CH];

__global__ void zero_stats_kernel() {
    int c = threadIdx.x;
    g_sum[c]   = 0.f;
    g_sqsum[c] = 0.f;
}

__device__ __forceinline__ uint32_t cvt_tf32(float f) {
    uint32_t r;
    asm("cvt.rna.tf32.f32 %0, %1;" : "=r"(r) : "f"(f));
    return r;
}

// ---------------- mask dtype detection (bool widened to ?) ----------------
__device__ __forceinline__ int detect_mask_mode(const void* mask) {
    int w = ((const int*)mask)[0];
    if (w == 1) return 1;                       // int32
    if (__int_as_float(w) == 1.0f) return 2;    // float32
    return 0;                                   // bytes
}
__device__ __forceinline__ bool mask_at(const void* mask, int mode, long i) {
    if (mode == 1) return ((const int*)mask)[i] != 0;
    if (mode == 2) return ((const float*)mask)[i] != 0.0f;
    return ((const unsigned char*)mask)[i] != 0;
}

// smem layout (bytes)
#define A_STRIDE 68               // 64 + 4 pad
#define B_STRIDE 136              // 128 + 8 pad
#define SM_VI 0                   // int[128]
#define SM_VO 512                 // int[128]
#define SM_A  1024                // u32[128*68]
#define SM_B  (SM_A + TILE_M * A_STRIDE * 4)
#define SM_TOTAL (SM_B + IN_CH * B_STRIDE * 4)    // 70656 B

// ---------------------------------------------------------------------------
// Per block: one k, 128 rules. Gather -> tf32 mma.sync (M=128,N=128,K=64)
// -> shfl-pack -> red.global.add.v4 scatter.
// grid = (ceil(R/128), 9), block = 256 (8 warps)
// warp w: M rows [ (w>>1)*32, +32 ), N cols [ (w&1)*64, +64 )
// ---------------------------------------------------------------------------
__global__ __launch_bounds__(256) void sp_mma_kernel(
    const float* __restrict__ feats,
    const float* __restrict__ W,
    const int*   __restrict__ in_idx,
    const int*   __restrict__ out_idx,
    const void*  __restrict__ mask,
    float* __restrict__ out,
    int R)
{
    extern __shared__ char smem[];
    int*      svi = (int*)(smem + SM_VI);
    int*      svo = (int*)(smem + SM_VO);
    uint32_t* sA  = (uint32_t*)(smem + SM_A);
    uint32_t* sB  = (uint32_t*)(smem + SM_B);

    const int tid  = threadIdx.x;
    const int warp = tid >> 5;
    const int lane = tid & 31;
    const int k    = blockIdx.y;

    // ---- rule metadata (threads 0..127 handle one rule each) ----
    const int mmode = detect_mask_mode(mask);
    bool valid = false;
    if (tid < TILE_M) {
        const long r = (long)blockIdx.x * TILE_M + tid;
        int vi = 0, vo = -1;
        if (r < R) {
            const long gi = (long)k * R + r;
            valid = mask_at(mask, mmode, gi);
            if (valid) { vi = in_idx[gi]; vo = out_idx[gi]; }
        }
        svi[tid] = vi;
        svo[tid] = vo;
    }
    // valid rules are front-packed per k-row -> padded tail blocks exit whole
    if (__syncthreads_count(tid < TILE_M ? (int)valid : 0) == 0) return;

    // ---- stage B = W[k] ([64 K][128 N], tf32, padded) ----
    {
        const float* Wk = W + (size_t)k * IN_CH * OUT_CH;
        #pragma unroll
        for (int i = 0; i < (IN_CH * OUT_CH) / 256; i++) {
            int idx = tid + i * 256;
            int c = idx >> 7, n = idx & 127;
            sB[c * B_STRIDE + n] = cvt_tf32(Wk[idx]);   // coalesced
        }
    }

    // ---- gather A rows (2 threads per row, 32 floats each) ----
    {
        const int row = tid >> 1, half = tid & 1;
        const int vi = svi[row];
        const bool rv = (svo[row] >= 0);
        const float4* src = (const float4*)(feats + (size_t)vi * IN_CH) + half * 8;
        uint4* dst = (uint4*)(sA + row * A_STRIDE + half * 32);
        #pragma unroll
        for (int j = 0; j < 8; j++) {
            uint4 o = make_uint4(0u, 0u, 0u, 0u);
            if (rv) {
                float4 v = src[j];
                o.x = cvt_tf32(v.x); o.y = cvt_tf32(v.y);
                o.z = cvt_tf32(v.z); o.w = cvt_tf32(v.w);
            }
            dst[j] = o;
        }
    }
    __syncthreads();

    // ---- MMA: each warp 2 M-tiles x 8 N-tiles, 8 K-steps of k=8 ----
    const int g = lane >> 2, t = lane & 3;
    const int mbase = (warp >> 1) * 32;
    const int nbase = (warp & 1) * 64;

    float acc[2][8][4];
    #pragma unroll
    for (int mt = 0; mt < 2; mt++)
        #pragma unroll
        for (int nt = 0; nt < 8; nt++)
            #pragma unroll
            for (int j = 0; j < 4; j++) acc[mt][nt][j] = 0.f;

    #pragma unroll
    for (int ks = 0; ks < 8; ks++) {
        const int k0 = ks * 8;
        uint32_t a[2][4];
        #pragma unroll
        for (int mt = 0; mt < 2; mt++) {
            const int rg = mbase + mt * 16 + g;
            a[mt][0] = sA[(rg)     * A_STRIDE + k0 + t];
            a[mt][1] = sA[(rg + 8) * A_STRIDE + k0 + t];
            a[mt][2] = sA[(rg)     * A_STRIDE + k0 + t + 4];
            a[mt][3] = sA[(rg + 8) * A_STRIDE + k0 + t + 4];
        }
        uint32_t b[8][2];
        #pragma unroll
        for (int nt = 0; nt < 8; nt++) {
            const int n = nbase + nt * 8 + g;
            b[nt][0] = sB[(k0 + t)     * B_STRIDE + n];
            b[nt][1] = sB[(k0 + t + 4) * B_STRIDE + n];
        }
        #pragma unroll
        for (int mt = 0; mt < 2; mt++)
            #pragma unroll
            for (int nt = 0; nt < 8; nt++)
                asm("mma.sync.aligned.m16n8k8.row.col.f32.tf32.tf32.f32 "
                    "{%0,%1,%2,%3}, {%4,%5,%6,%7}, {%8,%9}, {%0,%1,%2,%3};"
                    : "+f"(acc[mt][nt][0]), "+f"(acc[mt][nt][1]),
                      "+f"(acc[mt][nt][2]), "+f"(acc[mt][nt][3])
                    : "r"(a[mt][0]), "r"(a[mt][1]), "r"(a[mt][2]), "r"(a[mt][3]),
                      "r"(b[nt][0]), "r"(b[nt][1]));
    }

    // ---- epilogue: shfl-pack lane pairs -> red.global.add.v4 ----
    // lane t=2q holds cols (4q,4q+1) of rows g / g+8; partner t=2q+1 holds
    // (4q+2,4q+3). After bfly(1): even lane emits v4 for row r0, odd lane
    // emits v4 for row r0+8, both at cols nbase+8nt+4q.
    const int q4 = (t >> 1) * 4;
    const bool odd = (t & 1);
    #pragma unroll
    for (int mt = 0; mt < 2; mt++) {
        const int r0 = mbase + mt * 16 + g;
        const int vo = svo[odd ? (r0 + 8) : r0];
        #pragma unroll
        for (int nt = 0; nt < 8; nt++) {
            float p0 = __shfl_xor_sync(0xffffffffu, acc[mt][nt][0], 1);
            float p1 = __shfl_xor_sync(0xffffffffu, acc[mt][nt][1], 1);
            float p2 = __shfl_xor_sync(0xffffffffu, acc[mt][nt][2], 1);
            float p3 = __shfl_xor_sync(0xffffffffu, acc[mt][nt][3], 1);
            float v0, v1, v2, v3;
            if (!odd) { v0 = acc[mt][nt][0]; v1 = acc[mt][nt][1]; v2 = p0; v3 = p1; }
            else      { v0 = p2; v1 = p3; v2 = acc[mt][nt][2]; v3 = acc[mt][nt][3]; }
            if (vo >= 0) {
                float* op = out + (size_t)vo * OUT_CH + nbase + nt * 8 + q4;
                asm volatile("red.global.add.v4.f32 [%0], {%1,%2,%3,%4};" ::
                    "l"(op), "f"(v0), "f"(v1), "f"(v2), "f"(v3) : "memory");
            }
        }
    }
}

// ---------------- BN stats / finalize / apply (R6 measured-good path) -------
__global__ void stats_kernel(const float* __restrict__ out, int n_out) {
    const int c   = threadIdx.x & (OUT_CH - 1);
    const int sub = threadIdx.x >> 7;
    const int rpb = blockDim.x >> 7;
    float s = 0.f, q = 0.f;
    for (long row = (long)blockIdx.x * rpb + sub; row < n_out;
         row += (long)gridDim.x * rpb) {
        float v = out[row * OUT_CH + c];
        s += v;
        q = fmaf(v, v, q);
    }
    atomicAdd(&g_sum[c], s);
    atomicAdd(&g_sqsum[c], q);
}

__global__ void finalize_kernel(const float* __restrict__ gamma,
                                const float* __restrict__ beta,
                                float inv_n) {
    int c = threadIdx.x;
    float mean = g_sum[c] * inv_n;
    float var  = fmaf(-mean, mean, g_sqsum[c] * inv_n);
    float sc   = gamma[c] * rsqrtf(var + 1e-5f);
    g_scale[c] = sc;
    g_bias[c]  = fmaf(-mean, sc, beta[c]);
}

__global__ void bnrelu_kernel(float* __restrict__ out, long n4) {
    long i      = (long)blockIdx.x * blockDim.x + threadIdx.x;
    long stride = (long)gridDim.x * blockDim.x;
    float4* o4  = (float4*)out;
    for (; i < n4; i += stride) {
        float4 v = o4[i];
        int c = (int)(i & 31) * 4;
        float4 sc = *(const float4*)&g_scale[c];
        float4 bi = *(const float4*)&g_bias[c];
        v.x = fmaxf(fmaf(v.x, sc.x, bi.x), 0.f);
        v.y = fmaxf(fmaf(v.y, sc.y, bi.y), 0.f);
        v.z = fmaxf(fmaf(v.z, sc.z, bi.z), 0.f);
        v.w = fmaxf(fmaf(v.w, sc.w, bi.w), 0.f);
        o4[i] = v;
    }
}

extern "C" void kernel_launch(void* const* d_in, const int* in_sizes, int n_in,
                              void* d_out, int out_size) {
    const float* feats = (const float*)d_in[0];
    const float* W     = (const float*)d_in[1];
    const float* gamma = (const float*)d_in[2];
    const float* beta  = (const float*)d_in[3];
    const int*   inI   = (const int*)d_in[4];
    const int*   outI  = (const int*)d_in[5];
    const void*  mask  = (const void*)d_in[6];
    float* out = (float*)d_out;

    const int R     = in_sizes[4] / 9;
    const int n_out = out_size / OUT_CH;

    cudaMemsetAsync(d_out, 0, (size_t)out_size * sizeof(float));
    zero_stats_kernel<<<1, OUT_CH>>>();

    cudaFuncSetAttribute(sp_mma_kernel,
                         cudaFuncAttributeMaxDynamicSharedMemorySize, SM_TOTAL);
    dim3 grid((R + TILE_M - 1) / TILE_M, 9);
    sp_mma_kernel<<<grid, 256, SM_TOTAL>>>(feats, W, inI, outI, mask, out, R);

    stats_kernel<<<1024, 512>>>(out, n_out);
    finalize_kernel<<<1, OUT_CH>>>(gamma, beta, 1.0f / (float)n_out);

    long n4 = (long)out_size / 4;
    int bgrid = (int)((n4 + 255) / 256);
    if (bgrid > 4096) bgrid = 4096;
    bnrelu_kernel<<<bgrid, 256>>>(out, n4);
}